// round 4
// baseline (speedup 1.0000x reference)
#include <cuda_runtime.h>
#include <math.h>

// Problem constants (fixed shapes for this dataset)
#define CC      128              // channels
#define TT      1024             // time_step_len
#define BBATCH  32               // scenes
#define NNODES  (BBATCH*TT)      // 32768
#define NEDGE   (16*NNODES)      // 524288

// ---------------------------------------------------------------------------
// Device scratch (static __device__ arrays: allocation-free per harness rules)
// ---------------------------------------------------------------------------
__device__ float g_q[NNODES*CC];
__device__ float g_k[NNODES*CC];
__device__ float g_v[NNODES*CC];
__device__ float g_att[NNODES*CC];
__device__ int   g_cnt[NNODES];
__device__ int   g_off[NNODES];
__device__ int   g_cur[NNODES];
__device__ int   g_csr[NEDGE];
__device__ int   g_vl[BBATCH];
__device__ int   g_is64;         // 1 if index inputs are int64, else 0

// ---------------------------------------------------------------------------
// K0: dtype sniff + valid_lens normalization.
// valid_lens entries are >= 1, so an int64 buffer viewed as int32 has zeros at
// all odd word positions; an int32 buffer cannot (all 32 entries nonzero).
// ---------------------------------------------------------------------------
__global__ void sniff_kernel(const int* __restrict__ vl_raw)
{
    bool is64 = true;
    for (int i = 0; i < BBATCH; i++)
        if (vl_raw[2*i + 1] != 0) { is64 = false; break; }
    g_is64 = is64 ? 1 : 0;
    for (int i = 0; i < BBATCH; i++)
        g_vl[i] = is64 ? vl_raw[2*i] : vl_raw[i];
}

__device__ __forceinline__ int edge_at(const void* ei, int is64, size_t idx)
{
    return is64 ? (int)((const long long*)ei)[idx] : ((const int*)ei)[idx];
}

// ---------------------------------------------------------------------------
// K1: fused per-projection GEMM: out = x @ W^T + b  (grid.y selects q/k/v)
// Block: 64 rows x 128 cols, 256 threads, thread tile 4x8 (stride-16 mapping)
// ---------------------------------------------------------------------------
__global__ void qkv_kernel(const float* __restrict__ x,
                           const float* __restrict__ Wq, const float* __restrict__ bq,
                           const float* __restrict__ Wk, const float* __restrict__ bk,
                           const float* __restrict__ Wv, const float* __restrict__ bv)
{
    extern __shared__ float sm[];
    float* xT = sm;               // [128][65]  x transposed (k-major)
    float* wT = sm + 128*65;      // [128][129] W transposed (k-major)

    int which = blockIdx.y;
    const float* W    = (which==0) ? Wq : (which==1) ? Wk : Wv;
    const float* bias = (which==0) ? bq : (which==1) ? bk : bv;
    float* og         = (which==0) ? g_q : (which==1) ? g_k : g_v;

    int r0  = blockIdx.x * 64;
    int tid = threadIdx.x;
    int tx  = tid & 15, ty = tid >> 4;

    // load x tile transposed
    for (int idx = tid; idx < 64*32; idx += 256) {
        int r = idx >> 5, c4 = (idx & 31) << 2;
        float4 f = *(const float4*)(x + (size_t)(r0 + r)*CC + c4);
        xT[(c4+0)*65 + r] = f.x;
        xT[(c4+1)*65 + r] = f.y;
        xT[(c4+2)*65 + r] = f.z;
        xT[(c4+3)*65 + r] = f.w;
    }
    // load W transposed: wT[k][co], W stored [co][k]
    for (int idx = tid; idx < 128*32; idx += 256) {
        int co = idx >> 5, k4 = (idx & 31) << 2;
        float4 f = *(const float4*)(W + (size_t)co*CC + k4);
        wT[(k4+0)*129 + co] = f.x;
        wT[(k4+1)*129 + co] = f.y;
        wT[(k4+2)*129 + co] = f.z;
        wT[(k4+3)*129 + co] = f.w;
    }
    __syncthreads();

    float acc[4][8];
#pragma unroll
    for (int i = 0; i < 4; i++)
#pragma unroll
        for (int j = 0; j < 8; j++) acc[i][j] = 0.f;

#pragma unroll 4
    for (int kk = 0; kk < CC; kk++) {
        float a[4], b[8];
#pragma unroll
        for (int i = 0; i < 4; i++) a[i] = xT[kk*65 + ty + 16*i];
#pragma unroll
        for (int j = 0; j < 8; j++) b[j] = wT[kk*129 + tx + 16*j];
#pragma unroll
        for (int i = 0; i < 4; i++)
#pragma unroll
            for (int j = 0; j < 8; j++)
                acc[i][j] = fmaf(a[i], b[j], acc[i][j]);
    }

    float bb[8];
#pragma unroll
    for (int j = 0; j < 8; j++) bb[j] = bias[tx + 16*j];
#pragma unroll
    for (int i = 0; i < 4; i++) {
        int r = r0 + ty + 16*i;
#pragma unroll
        for (int j = 0; j < 8; j++)
            og[(size_t)r*CC + tx + 16*j] = acc[i][j] + bb[j];
    }
}

// ---------------------------------------------------------------------------
// K2: flash-attention fp32. Column-only mask => iterate s-chunks < L only.
// Block: 64 q-rows, chunks of 64 kv-rows, 256 threads.
// ---------------------------------------------------------------------------
__global__ void attn_kernel()
{
    extern __shared__ float sm[];
    float* qT = sm;                         // [128][65]
    float* kT = qT + 128*65;                // [128][65]
    float* vs = kT + 128*65;                // [64][128]
    float* pT = vs + 64*128;                // [64][65]  P transposed (s-major)

    int b   = blockIdx.y;
    int t0  = blockIdx.x * 64;
    int L   = g_vl[b];
    int tid = threadIdx.x;
    int tx  = tid & 15, ty = tid >> 4;

    const float* qg = g_q + (size_t)(b*TT + t0)*CC;
    const float* kg = g_k + (size_t)(b*TT)*CC;
    const float* vg = g_v + (size_t)(b*TT)*CC;

    // load q tile transposed
    for (int idx = tid; idx < 64*32; idx += 256) {
        int r = idx >> 5, c4 = (idx & 31) << 2;
        float4 f = *(const float4*)(qg + (size_t)r*CC + c4);
        qT[(c4+0)*65 + r] = f.x;
        qT[(c4+1)*65 + r] = f.y;
        qT[(c4+2)*65 + r] = f.z;
        qT[(c4+3)*65 + r] = f.w;
    }

    float m[4], l[4], o[4][8];
#pragma unroll
    for (int i = 0; i < 4; i++) {
        m[i] = -1e30f; l[i] = 0.f;
#pragma unroll
        for (int j = 0; j < 8; j++) o[i][j] = 0.f;
    }
    __syncthreads();

    for (int s0 = 0; s0 < L; s0 += 64) {
        // load k chunk transposed + v chunk straight
        for (int idx = tid; idx < 64*32; idx += 256) {
            int r = idx >> 5, c4 = (idx & 31) << 2;
            const float* kr = kg + (size_t)(s0 + r)*CC + c4;
            const float* vr = vg + (size_t)(s0 + r)*CC + c4;
            float4 f = *(const float4*)kr;
            float4 g2 = *(const float4*)vr;
            kT[(c4+0)*65 + r] = f.x;
            kT[(c4+1)*65 + r] = f.y;
            kT[(c4+2)*65 + r] = f.z;
            kT[(c4+3)*65 + r] = f.w;
            *(float4*)(vs + r*CC + c4) = g2;
        }
        __syncthreads();

        // S = q . k^T   (64x64)
        float acc[4][4];
#pragma unroll
        for (int i = 0; i < 4; i++)
#pragma unroll
            for (int j = 0; j < 4; j++) acc[i][j] = 0.f;

#pragma unroll 4
        for (int kk = 0; kk < CC; kk++) {
            float a[4], bbv[4];
#pragma unroll
            for (int i = 0; i < 4; i++) a[i]  = qT[kk*65 + ty + 16*i];
#pragma unroll
            for (int j = 0; j < 4; j++) bbv[j] = kT[kk*65 + tx + 16*j];
#pragma unroll
            for (int i = 0; i < 4; i++)
#pragma unroll
                for (int j = 0; j < 4; j++)
                    acc[i][j] = fmaf(a[i], bbv[j], acc[i][j]);
        }

        // online softmax per row (rows ty+16i; reduce across 16 tx lanes)
        bool valid[4];
#pragma unroll
        for (int j = 0; j < 4; j++) valid[j] = (s0 + tx + 16*j) < L;

#pragma unroll
        for (int i = 0; i < 4; i++) {
            float mx = -1e30f;
#pragma unroll
            for (int j = 0; j < 4; j++)
                if (valid[j]) mx = fmaxf(mx, acc[i][j]);
#pragma unroll
            for (int w = 1; w < 16; w <<= 1)
                mx = fmaxf(mx, __shfl_xor_sync(0xffffffffu, mx, w));
            float mn = fmaxf(m[i], mx);
            float sc = __expf(m[i] - mn);
            float p[4]; float rs = 0.f;
#pragma unroll
            for (int j = 0; j < 4; j++) {
                p[j] = valid[j] ? __expf(acc[i][j] - mn) : 0.f;
                rs += p[j];
            }
#pragma unroll
            for (int w = 1; w < 16; w <<= 1)
                rs += __shfl_xor_sync(0xffffffffu, rs, w);
            l[i] = l[i]*sc + rs;
            m[i] = mn;
#pragma unroll
            for (int j = 0; j < 8; j++) o[i][j] *= sc;
            // store P transposed: pT[s][row]
#pragma unroll
            for (int j = 0; j < 4; j++)
                pT[(tx + 16*j)*65 + ty + 16*i] = p[j];
        }
        __syncthreads();

        // O += P @ V   (64x128)
#pragma unroll 4
        for (int kk = 0; kk < 64; kk++) {
            float a[4], bbv[8];
#pragma unroll
            for (int i = 0; i < 4; i++) a[i]  = pT[kk*65 + ty + 16*i];
#pragma unroll
            for (int j = 0; j < 8; j++) bbv[j] = vs[kk*CC + tx + 16*j];
#pragma unroll
            for (int i = 0; i < 4; i++)
#pragma unroll
                for (int j = 0; j < 8; j++)
                    o[i][j] = fmaf(a[i], bbv[j], o[i][j]);
        }
        __syncthreads();
    }

    // normalize + store
#pragma unroll
    for (int i = 0; i < 4; i++) {
        float inv = 1.f / l[i];
        int r = b*TT + t0 + ty + 16*i;
#pragma unroll
        for (int j = 0; j < 8; j++)
            g_att[(size_t)r*CC + tx + 16*j] = o[i][j] * inv;
    }
}

// ---------------------------------------------------------------------------
// K3: CSR-by-dst build + gather-sum (no float atomics)
// ---------------------------------------------------------------------------
__global__ void zero_cnt_kernel()
{
    int i = blockIdx.x*256 + threadIdx.x;
    if (i < NNODES) g_cnt[i] = 0;
}

__global__ void hist_kernel(const void* __restrict__ ei)
{
    int e = blockIdx.x*256 + threadIdx.x;
    int is64 = g_is64;
    if (e < NEDGE) {
        int d = edge_at(ei, is64, (size_t)NEDGE + e);   // dst row
        atomicAdd(&g_cnt[d], 1);
    }
}

__global__ void scan_kernel()
{
    __shared__ int ssum[1024];
    int tid = threadIdx.x;
    int base = tid * 32;
    int loc[32];
    int s = 0;
#pragma unroll
    for (int i = 0; i < 32; i++) { loc[i] = s; s += g_cnt[base + i]; }
    ssum[tid] = s;
    __syncthreads();
    for (int off = 1; off < 1024; off <<= 1) {
        int v = (tid >= off) ? ssum[tid - off] : 0;
        __syncthreads();
        ssum[tid] += v;
        __syncthreads();
    }
    int pre = (tid == 0) ? 0 : ssum[tid - 1];
#pragma unroll
    for (int i = 0; i < 32; i++) {
        int o = pre + loc[i];
        g_off[base + i] = o;
        g_cur[base + i] = o;
    }
}

__global__ void scatter_kernel(const void* __restrict__ ei)
{
    int e = blockIdx.x*256 + threadIdx.x;
    int is64 = g_is64;
    if (e < NEDGE) {
        int srcn = edge_at(ei, is64, (size_t)e);
        int d    = edge_at(ei, is64, (size_t)NEDGE + e);
        int p = atomicAdd(&g_cur[d], 1);
        g_csr[p] = srcn;
    }
}

__global__ void gather_kernel(float* __restrict__ out)
{
    __shared__ int srcs[512];
    int n   = blockIdx.x;
    int tid = threadIdx.x;              // 128 threads, one per channel
    int start = g_off[n];
    int cnt   = g_cnt[n];
    float acc = 0.f;
    for (int base = 0; base < cnt; base += 512) {
        int nn = min(512, cnt - base);
        for (int j = tid; j < nn; j += 128) srcs[j] = g_csr[start + base + j];
        __syncthreads();
#pragma unroll 4
        for (int j = 0; j < nn; j++)
            acc += g_att[(size_t)srcs[j]*CC + tid];
        __syncthreads();
    }
    out[(size_t)n*CC + tid] = acc;
}

// ---------------------------------------------------------------------------
// Launch
// ---------------------------------------------------------------------------
extern "C" void kernel_launch(void* const* d_in, const int* in_sizes, int n_in,
                              void* d_out, int out_size)
{
    const float* x  = (const float*)d_in[0];
    const void*  ei = d_in[1];                 // int32 or int64 (sniffed on device)
    const int*   vl = (const int*)d_in[2];     // raw words; sniffed on device

    // time_step_len may or may not appear as a size-1 input; find Wq robustly.
    int wi = 3;
    while (wi < n_in && in_sizes[wi] != CC*CC) wi++;
    const float* Wq = (const float*)d_in[wi+0];
    const float* bq = (const float*)d_in[wi+1];
    const float* Wk = (const float*)d_in[wi+2];
    const float* bk = (const float*)d_in[wi+3];
    const float* Wv = (const float*)d_in[wi+4];
    const float* bv = (const float*)d_in[wi+5];
    float* out = (float*)d_out;

    const int smem_qkv  = (128*65 + 128*129) * 4;                 // 99328 B
    const int smem_attn = (128*65*2 + 64*128 + 64*65) * 4;        // 115968 B
    cudaFuncSetAttribute(qkv_kernel,  cudaFuncAttributeMaxDynamicSharedMemorySize, smem_qkv);
    cudaFuncSetAttribute(attn_kernel, cudaFuncAttributeMaxDynamicSharedMemorySize, smem_attn);

    sniff_kernel<<<1, 1>>>(vl);
    qkv_kernel<<<dim3(NNODES/64, 3), 256, smem_qkv>>>(x, Wq, bq, Wk, bk, Wv, bv);
    attn_kernel<<<dim3(TT/64, BBATCH), 256, smem_attn>>>();
    zero_cnt_kernel<<<(NNODES+255)/256, 256>>>();
    hist_kernel<<<(NEDGE+255)/256, 256>>>(ei);
    scan_kernel<<<1, 1024>>>();
    scatter_kernel<<<(NEDGE+255)/256, 256>>>(ei);
    gather_kernel<<<NNODES, 128>>>(out);
}